// round 14
// baseline (speedup 1.0000x reference)
#include <cuda_runtime.h>
#include <math.h>

// PDELayer: 8192 x (48x48) grids, 100 explicit diffusion steps.
// BATCH-PACKED f32x2 (2 grids/CTA) + WARP-SHUFFLE horizontal exchange.
// R13 post-mortem: SMEM crossbar was the binder (32 shared ops/thread/step).
// Now: left/right neighbors travel via __shfl within 16-lane rows (register
// crossbar, not SMEM); only the 2 vertical boundary rows are exchanged via
// SMEM (6 LDS.64 + 6 STS.64 per thread per step, 0.375x traffic).
// Grid-edge lanes patch in the TIME-INVARIANT reflect halo (reference pads
// once and never updates the pad) via predicated single-lane LDS.
// 5-op cc-form per cell: n = cc*u + A[r]*(up+dn) + B[c]*(lf+rt), cc=1-2A-2B.
// 128 threads (16x8), each owns a 3-wide x 6-tall pack tile in registers.

#define NG     48
#define PR     50      // padded rows
#define SS     52      // padded row stride (in packs)
#define NSTEPS 100
#define TW     3
#define TH     6
#define NTHR   128

typedef unsigned long long ull;

__device__ __forceinline__ ull f2fma(ull a, ull b, ull c) {
    ull d; asm("fma.rn.f32x2 %0,%1,%2,%3;" : "=l"(d) : "l"(a), "l"(b), "l"(c)); return d;
}
__device__ __forceinline__ ull f2add(ull a, ull b) {
    ull d; asm("add.rn.f32x2 %0,%1,%2;" : "=l"(d) : "l"(a), "l"(b)); return d;
}
__device__ __forceinline__ ull f2mul(ull a, ull b) {
    ull d; asm("mul.rn.f32x2 %0,%1,%2;" : "=l"(d) : "l"(a), "l"(b)); return d;
}
__device__ __forceinline__ ull pk(float lo, float hi) {
    ull v; asm("mov.b64 %0,{%1,%2};" : "=l"(v) : "f"(lo), "f"(hi)); return v;
}
__device__ __forceinline__ void unpk(ull v, float& lo, float& hi) {
    asm("mov.b64 {%0,%1},%2;" : "=f"(lo), "=f"(hi) : "l"(v));
}

template <bool STORE>
__device__ __forceinline__ void step_tile(
    const ull* __restrict__ cur, ull* __restrict__ nxt,
    ull u[TH][TW], const ull A2[TH], const ull B20, const ull B21, const ull B22,
    const ull cc[TH][TW], int R0, int C0, int tx)
{
    // vertical neighbor rows (SMEM; halo rows are time-invariant and always valid)
    ull top0 = cur[(R0 - 1) * SS + C0 + 0];
    ull top1 = cur[(R0 - 1) * SS + C0 + 1];
    ull top2 = cur[(R0 - 1) * SS + C0 + 2];
    ull bot0 = cur[(R0 + TH) * SS + C0 + 0];
    ull bot1 = cur[(R0 + TH) * SS + C0 + 1];
    ull bot2 = cur[(R0 + TH) * SS + C0 + 2];

    ull pv0 = 0, pv1 = 0, pv2 = 0;   // old u[r-1]
#pragma unroll
    for (int r = 0; r < TH; r++) {
        // horizontal neighbors via register shuffle (old values, pre-update)
        ull lf = __shfl_up_sync  (0xffffffffu, u[r][2], 1, 16);
        ull rt = __shfl_down_sync(0xffffffffu, u[r][0], 1, 16);
        // grid-edge lanes read the time-invariant reflect halo columns
        if (tx == 0)  lf = cur[(R0 + r) * SS + 0];
        if (tx == 15) rt = cur[(R0 + r) * SS + (PR - 1)];

        ull c0 = u[r][0], c1 = u[r][1], c2 = u[r][2];

        ull up0 = (r == 0) ? top0 : pv0;
        ull up1 = (r == 0) ? top1 : pv1;
        ull up2 = (r == 0) ? top2 : pv2;
        ull dn0 = (r == TH - 1) ? bot0 : u[r + 1][0];
        ull dn1 = (r == TH - 1) ? bot1 : u[r + 1][1];
        ull dn2 = (r == TH - 1) ? bot2 : u[r + 1][2];

        // 5 packed ops per pack-cell: n = cc*u + A*(up+dn) + B*(lf+rt)
        ull n0 = f2mul(cc[r][0], c0);
        n0 = f2fma(A2[r], f2add(up0, dn0), n0);
        n0 = f2fma(B20,   f2add(lf,  c1),  n0);

        ull n1 = f2mul(cc[r][1], c1);
        n1 = f2fma(A2[r], f2add(up1, dn1), n1);
        n1 = f2fma(B21,   f2add(c0,  c2),  n1);

        ull n2 = f2mul(cc[r][2], c2);
        n2 = f2fma(A2[r], f2add(up2, dn2), n2);
        n2 = f2fma(B22,   f2add(c1,  rt),  n2);

        if (STORE && (r == 0 || r == TH - 1)) {
            ull* nrow = &nxt[(R0 + r) * SS + C0];
            nrow[0] = n0; nrow[1] = n1; nrow[2] = n2;
        }

        pv0 = c0; pv1 = c1; pv2 = c2;
        u[r][0] = n0; u[r][1] = n1; u[r][2] = n2;
    }
    if (STORE) __syncthreads();
}

__global__ __launch_bounds__(NTHR, 4)
void pde_stencil_kernel(const float* __restrict__ u0,
                        const float* __restrict__ a1p, const float* __restrict__ a2p,
                        const float* __restrict__ a3p, const float* __restrict__ b1p,
                        const float* __restrict__ b2p, const float* __restrict__ b3p,
                        float* __restrict__ out)
{
    __shared__ __align__(16) ull buf0[PR * SS];
    __shared__ __align__(16) ull buf1[PR * SS];

    const int b   = blockIdx.x;          // pair index: grids 2b, 2b+1
    const int tid = threadIdx.x;
    const int tx  = tid & 15;            // 0..15
    const int ty  = tid >> 4;            // 0..7

    const float* g0 = u0  + (size_t)(2 * b)     * (NG * NG);
    const float* g1 = u0  + (size_t)(2 * b + 1) * (NG * NG);
    float*       o0 = out + (size_t)(2 * b)     * (NG * NG);
    float*       o1 = out + (size_t)(2 * b + 1) * (NG * NG);

    // ---- load interior of BOTH grids into buf0 packs (coalesced gmem) ----
#pragma unroll
    for (int k = 0; k < 18; k++) {
        int c = tid + NTHR * k;             // 0..2303
        int i = c / NG, j = c % NG;
        buf0[(i + 1) * SS + (j + 1)] = pk(g0[c], g1[c]);
    }
    __syncthreads();

    // ---- reflect halo (time-invariant) into BOTH buffers ----
    for (int h = tid; h < 196; h += NTHR) {
        int ii, jj;
        if      (h < 50)  { ii = 0;         jj = h;        }
        else if (h < 100) { ii = 49;        jj = h - 50;   }
        else if (h < 148) { ii = h - 99;    jj = 0;        }   // 1..48
        else              { ii = h - 147;   jj = 49;       }   // 1..48
        int si = (ii == 0) ? 2 : (ii == 49) ? 47 : ii;
        int sj = (jj == 0) ? 2 : (jj == 49) ? 47 : jj;
        ull v = buf0[si * SS + sj];
        buf0[ii * SS + jj] = v;
        buf1[ii * SS + jj] = v;
    }

    // ---- coefficients (batch-invariant; packed as broadcast pairs) ----
    const float aw1 = fabsf(*a1p), aw2 = fabsf(*a2p), aw3 = fabsf(*a3p);
    const float bw1 = fabsf(*b1p), bw2 = fabsf(*b2p), bw3 = fabsf(*b3p);
    const float CA = 0.1152f;                 // 0.5*DT/DX^2
    const float CB = 0.2304f;                 // DT/DY^2
    const float TP = 6.283185307179586f;
    const float INV47 = 1.0f / 47.0f;

    const int R0 = 1 + TH * ty;
    const int C0 = 1 + TW * tx;

    float Av[TH];
    ull A2[TH];
#pragma unroll
    for (int r = 0; r < TH; r++) {
        float t = (float)(TH * ty + r) * INV47;
        Av[r] = CA * (aw1 + aw2 * sinf(TP * t) + aw3 * cosf(TP * t));
        A2[r] = pk(Av[r], Av[r]);
    }
    float Bv[TW];
    ull B2[TW];
#pragma unroll
    for (int c = 0; c < TW; c++) {
        float t = (float)(TW * tx + c) * INV47;
        Bv[c] = CB * (bw1 + bw2 * cosf(TP * t) + bw3 * sinf(TP * t));
        B2[c] = pk(Bv[c], Bv[c]);
    }
    const ull B20 = B2[0], B21 = B2[1], B22 = B2[2];

    // time-invariant center coefficient packs: cc = 1 - 2A[r] - 2B[c]
    ull cc[TH][TW];
#pragma unroll
    for (int r = 0; r < TH; r++)
#pragma unroll
        for (int c = 0; c < TW; c++) {
            float v = 1.0f - 2.0f * (Av[r] + Bv[c]);
            cc[r][c] = pk(v, v);
        }

    __syncthreads();   // interior + halo visible

    // ---- own pack tile into registers ----
    ull u[TH][TW];
#pragma unroll
    for (int r = 0; r < TH; r++)
#pragma unroll
        for (int c = 0; c < TW; c++)
            u[r][c] = buf0[(R0 + r) * SS + C0 + c];

    // ---- 100 steps: double-steps, final step skips stores+barrier ----
    for (int s = 0; s < NSTEPS - 2; s += 2) {
        step_tile<true>(buf0, buf1, u, A2, B20, B21, B22, cc, R0, C0, tx);
        step_tile<true>(buf1, buf0, u, A2, B20, B21, B22, cc, R0, C0, tx);
    }
    step_tile<true >(buf0, buf1, u, A2, B20, B21, B22, cc, R0, C0, tx);
    step_tile<false>(buf1, buf0, u, A2, B20, B21, B22, cc, R0, C0, tx);

    // ---- writeback both grids straight from registers ----
#pragma unroll
    for (int r = 0; r < TH; r++)
#pragma unroll
        for (int c = 0; c < TW; c++) {
            float lo, hi;
            unpk(u[r][c], lo, hi);
            int gi = (TH * ty + r) * NG + (TW * tx + c);
            o0[gi] = lo;
            o1[gi] = hi;
        }
}

extern "C" void kernel_launch(void* const* d_in, const int* in_sizes, int n_in,
                              void* d_out, int out_size)
{
    const float* u0 = (const float*)d_in[0];
    const float* a1 = (const float*)d_in[1];
    const float* a2 = (const float*)d_in[2];
    const float* a3 = (const float*)d_in[3];
    const float* b1 = (const float*)d_in[4];
    const float* b2 = (const float*)d_in[5];
    const float* b3 = (const float*)d_in[6];
    float* out = (float*)d_out;

    static int carveout_set = 0;
    if (!carveout_set) {
        cudaFuncSetAttribute(pde_stencil_kernel,
                             cudaFuncAttributePreferredSharedMemoryCarveout, 100);
        carveout_set = 1;
    }

    int nb = in_sizes[0] / (2 * NG * NG);   // 4096 grid pairs
    pde_stencil_kernel<<<nb, NTHR>>>(u0, a1, a2, a3, b1, b2, b3, out);
}

// round 15
// speedup vs baseline: 1.2626x; 1.2626x over previous
#include <cuda_runtime.h>
#include <math.h>

// PDELayer: 8192 x (48x48) grids, 100 explicit diffusion steps.
// BATCH-PACKED f32x2 (2 grids/CTA). 64 threads (8x4), each owns a 6x6 pack
// tile in registers -> perimeter/area minimized: 44 shared ops/thread/step
// (24 LDS.64 + 20 STS.64) vs 56 for 3x12 (R12) and 32@128thr (R13).
// Bank fix: 6*tx spans all even bank-pairs mod 16, so 6-row blocks are offset
// by s(R)=((R+5)/6)&1 packs -> adjacent ty groups use odd vs even bank-pair
// sets; every 16-lane wavefront is conflict-free.
// Double-buffered SMEM, 1 barrier/step, m2-form (6 packed fma-pipe ops/pack).
// Reflect halo is time-invariant (reference pads once, updates interior only).

#define NG     48
#define SS     54      // padded row stride (in packs)
#define NSTEPS 100
#define TWD    6
#define THT    6
#define NTHR   64

typedef unsigned long long ull;

__device__ __forceinline__ ull f2fma(ull a, ull b, ull c) {
    ull d; asm("fma.rn.f32x2 %0,%1,%2,%3;" : "=l"(d) : "l"(a), "l"(b), "l"(c)); return d;
}
__device__ __forceinline__ ull f2add(ull a, ull b) {
    ull d; asm("add.rn.f32x2 %0,%1,%2;" : "=l"(d) : "l"(a), "l"(b)); return d;
}
__device__ __forceinline__ ull pk(float lo, float hi) {
    ull v; asm("mov.b64 %0,{%1,%2};" : "=l"(v) : "f"(lo), "f"(hi)); return v;
}
__device__ __forceinline__ void unpk(ull v, float& lo, float& hi) {
    asm("mov.b64 {%0,%1},%2;" : "=f"(lo), "=f"(hi) : "l"(v));
}

// pack index of padded cell (R,C), R,C in 0..49; +s(R) row-block parity shift
__device__ __forceinline__ int sidx(int R, int C) {
    return R * SS + C + (((R + 5) / 6) & 1);
}

template <bool STORE>
__device__ __forceinline__ void step_tile(
    const ull* __restrict__ cur, ull* __restrict__ nxt,
    ull u[THT][TWD], const ull A2[THT], const ull B2[TWD], const ull m2,
    int baseOwn, int baseTop, int baseBot)   // precomputed pack bases
{
    ull top[TWD], bot[TWD];
#pragma unroll
    for (int c = 0; c < TWD; c++) {
        top[c] = cur[baseTop + c];
        bot[c] = cur[baseBot + c];
    }

    ull pv[TWD];
#pragma unroll
    for (int r = 0; r < THT; r++) {
        int rowBase = baseOwn + r * SS;
        ull lf = cur[rowBase - 1];
        ull rt = cur[rowBase + TWD];

        ull n[TWD];
#pragma unroll
        for (int c = 0; c < TWD; c++) {
            ull cen = u[r][c];
            ull up  = (r == 0) ? top[c] : pv[c];
            ull dn  = (r == THT - 1) ? bot[c] : u[r + 1][c];
            ull lft = (c == 0) ? lf : u[r][c - 1];
            ull rgt = (c == TWD - 1) ? rt : u[r][c + 1];

            ull sx = f2fma(m2, cen, f2add(up, dn));
            ull nv = f2fma(A2[r], sx, cen);
            ull sy = f2fma(m2, cen, f2add(lft, rgt));
            nv     = f2fma(B2[c], sy, nv);
            n[c] = nv;
        }

        if (STORE) {
            if (r == 0 || r == THT - 1) {
#pragma unroll
                for (int c = 0; c < TWD; c++) nxt[rowBase + c] = n[c];
            } else {
                nxt[rowBase] = n[0];
                nxt[rowBase + TWD - 1] = n[TWD - 1];
            }
        }

#pragma unroll
        for (int c = 0; c < TWD; c++) { pv[c] = u[r][c]; u[r][c] = n[c]; }
    }
    if (STORE) __syncthreads();
}

__global__ __launch_bounds__(NTHR, 5)
void pde_stencil_kernel(const float* __restrict__ u0,
                        const float* __restrict__ a1p, const float* __restrict__ a2p,
                        const float* __restrict__ a3p, const float* __restrict__ b1p,
                        const float* __restrict__ b2p, const float* __restrict__ b3p,
                        float* __restrict__ out)
{
    __shared__ __align__(16) ull buf0[50 * SS + 2];
    __shared__ __align__(16) ull buf1[50 * SS + 2];

    const int b   = blockIdx.x;          // pair index: grids 2b, 2b+1
    const int tid = threadIdx.x;
    const int tx  = tid & 7;             // 0..7
    const int ty  = tid >> 3;            // 0..7  (8x8 tile layout)

    const float* g0 = u0  + (size_t)(2 * b)     * (NG * NG);
    const float* g1 = u0  + (size_t)(2 * b + 1) * (NG * NG);
    float*       o0 = out + (size_t)(2 * b)     * (NG * NG);
    float*       o1 = out + (size_t)(2 * b + 1) * (NG * NG);

    // ---- load interior of BOTH grids into buf0 packs (coalesced gmem) ----
#pragma unroll
    for (int k = 0; k < 36; k++) {
        int c = tid + NTHR * k;             // 0..2303
        int i = c / NG, j = c % NG;
        buf0[sidx(i + 1, j + 1)] = pk(g0[c], g1[c]);
    }
    __syncthreads();

    // ---- reflect halo (time-invariant) into BOTH buffers ----
    for (int h = tid; h < 196; h += NTHR) {
        int ii, jj;
        if      (h < 50)  { ii = 0;         jj = h;        }
        else if (h < 100) { ii = 49;        jj = h - 50;   }
        else if (h < 148) { ii = h - 99;    jj = 0;        }   // 1..48
        else              { ii = h - 147;   jj = 49;       }   // 1..48
        int si = (ii == 0) ? 2 : (ii == 49) ? 47 : ii;
        int sj = (jj == 0) ? 2 : (jj == 49) ? 47 : jj;
        ull v = buf0[sidx(si, sj)];
        buf0[sidx(ii, jj)] = v;
        buf1[sidx(ii, jj)] = v;
    }

    // ---- coefficients (batch-invariant; packed as broadcast pairs) ----
    const float aw1 = fabsf(*a1p), aw2 = fabsf(*a2p), aw3 = fabsf(*a3p);
    const float bw1 = fabsf(*b1p), bw2 = fabsf(*b2p), bw3 = fabsf(*b3p);
    const float CA = 0.1152f;                 // 0.5*DT/DX^2
    const float CB = 0.2304f;                 // DT/DY^2
    const float TP = 6.283185307179586f;
    const float INV47 = 1.0f / 47.0f;

    const int R0 = 1 + THT * ty;
    const int C0 = 1 + TWD * tx;

    ull A2[THT];
#pragma unroll
    for (int r = 0; r < THT; r++) {
        float t = (float)(THT * ty + r) * INV47;
        float a = CA * (aw1 + aw2 * sinf(TP * t) + aw3 * cosf(TP * t));
        A2[r] = pk(a, a);
    }
    ull B2[TWD];
#pragma unroll
    for (int c = 0; c < TWD; c++) {
        float t = (float)(TWD * tx + c) * INV47;
        float v = CB * (bw1 + bw2 * cosf(TP * t) + bw3 * sinf(TP * t));
        B2[c] = pk(v, v);
    }
    const ull m2 = pk(-2.0f, -2.0f);

    // pack-index bases (row-block shift is constant per block of 6 rows)
    const int baseOwn = sidx(R0, C0);          // rows R0..R0+5 share s
    const int baseTop = sidx(R0 - 1, C0);
    const int baseBot = sidx(R0 + THT, C0);

    __syncthreads();   // interior + halo visible

    // ---- own pack tile into registers ----
    ull u[THT][TWD];
#pragma unroll
    for (int r = 0; r < THT; r++)
#pragma unroll
        for (int c = 0; c < TWD; c++)
            u[r][c] = buf0[baseOwn + r * SS + c];

    // ---- 100 steps: double-steps, final step skips stores+barrier ----
    for (int s = 0; s < NSTEPS - 2; s += 2) {
        step_tile<true>(buf0, buf1, u, A2, B2, m2, baseOwn, baseTop, baseBot);
        step_tile<true>(buf1, buf0, u, A2, B2, m2, baseOwn, baseTop, baseBot);
    }
    step_tile<true >(buf0, buf1, u, A2, B2, m2, baseOwn, baseTop, baseBot);
    step_tile<false>(buf1, buf0, u, A2, B2, m2, baseOwn, baseTop, baseBot);

    // ---- writeback both grids straight from registers ----
#pragma unroll
    for (int r = 0; r < THT; r++)
#pragma unroll
        for (int c = 0; c < TWD; c++) {
            float lo, hi;
            unpk(u[r][c], lo, hi);
            int gi = (THT * ty + r) * NG + (TWD * tx + c);
            o0[gi] = lo;
            o1[gi] = hi;
        }
}

extern "C" void kernel_launch(void* const* d_in, const int* in_sizes, int n_in,
                              void* d_out, int out_size)
{
    const float* u0 = (const float*)d_in[0];
    const float* a1 = (const float*)d_in[1];
    const float* a2 = (const float*)d_in[2];
    const float* a3 = (const float*)d_in[3];
    const float* b1 = (const float*)d_in[4];
    const float* b2 = (const float*)d_in[5];
    const float* b3 = (const float*)d_in[6];
    float* out = (float*)d_out;

    static int carveout_set = 0;
    if (!carveout_set) {
        cudaFuncSetAttribute(pde_stencil_kernel,
                             cudaFuncAttributePreferredSharedMemoryCarveout, 100);
        carveout_set = 1;
    }

    int nb = in_sizes[0] / (2 * NG * NG);   // 4096 grid pairs
    pde_stencil_kernel<<<nb, NTHR>>>(u0, a1, a2, a3, b1, b2, b3, out);
}